// round 16
// baseline (speedup 1.0000x reference)
#include <cuda_runtime.h>

// D2Q9 LBM single step — single-kernel, single-barrier, TH=16 tile,
// dynamic smem, streaming stores.
//   Phase 1: stream f tile rows (aligned uint4) + per-cell rho/u into smem.
//   Phase 2: stream-gather + collide-at-gather + bounce-back + macro + store.
// Mask proven 4-byte (R5/R6 A-B test): nonzero == solid for int32 and f32.
//
//   f    [2048,2048,9]  f32      rho [2048,2048] f32
//   u    [2048,2048,2]  f32      mask[2048,2048] 4-byte bool
//   out  [2048,2048,12] f32  (f_new[9], rho_new, ux, uy)
// jnp.roll(a, shift=e) => new[x,y] = old[x-ex, y-ey] (periodic &2047).

#define NXg 2048
#define NYg 2048
#define WRAP(v) ((v) & 2047)

#define TW 64                  // tile width (y, contiguous)
#define TH 16                  // tile height (x)
#define NROWS (TH + 2)         // 18 rows incl. halo
// f smem row: [inner 64 cells * 9 = 576 | hy=0 edge: 9 | hy=65 edge: 9] + pad
#define RSTRIDE 596
#define EDGE_LO 576
#define EDGE_HI 585
#define ROW_U4 144             // uint4 copies per inner row span
#define NU4 (NROWS * ROW_U4)   // 2592
#define CW 66                  // coeff row width (halo coord hy 0..65)

#define FS_FLOATS (NROWS * RSTRIDE)            // 10728
#define RS_FLOATS (NROWS * CW)                 // 1188
#define SMEM_BYTES ((FS_FLOATS + RS_FLOATS) * 4 + NROWS * CW * 8)  // 57168

__global__ __launch_bounds__(512, 3)
void lbm_step_kernel(const float*        __restrict__ f,
                     const float*        __restrict__ rho,
                     const float2*       __restrict__ u,
                     const unsigned int* __restrict__ mask,
                     float*              __restrict__ out)
{
    extern __shared__ float smem[];
    float*  fs = smem;                               // 42.9 KB
    float*  rS = smem + FS_FLOATS;                   //  4.75 KB
    float2* uS = reinterpret_cast<float2*>(smem + FS_FLOATS + RS_FLOATS); // 9.5 KB

    const int tid = threadIdx.x;
    const int Y0  = blockIdx.x * TW;
    const int X0  = blockIdx.y * TH;
    const int ly  = tid & 63;
    const int lx0 = tid >> 6;            // 0..7

    // Mask loads first (latency hidden behind phase 1)
    bool solid[2];
    #pragma unroll
    for (int cp = 0; cp < 2; cp++) {
        const unsigned cell = (unsigned)(X0 + lx0 + 8 * cp) * NYg + (Y0 + ly);
        solid[cp] = (mask[cell] != 0u);
    }

    // ---- Phase 1a: bulk f copy (aligned uint4, perfectly coalesced) ----
    #pragma unroll
    for (int k = 0; k < 6; k++) {
        const int idx = k * 512 + tid;
        if (k < 5 || idx < NU4) {
            const int r   = idx / ROW_U4;         // constant div -> mul.hi
            const int col = idx - r * ROW_U4;
            const int gx  = WRAP(X0 + r - 1);
            const size_t basef = ((size_t)gx * NYg + Y0) * 9;   // 16B aligned
            const uint4 v = *reinterpret_cast<const uint4*>(f + basef + col * 4);
            *reinterpret_cast<uint4*>(&fs[r * RSTRIDE + col * 4]) = v;
        }
    }

    // ---- Phase 1b: per-cell rho/u (+ edge-cell f) ----
    #pragma unroll
    for (int k = 0; k < 3; k++) {
        const int c = k * 512 + tid;
        if (c < NROWS * 64) {                 // 1152 inner-span cells
            const int r = c >> 6, cy = c & 63;
            const int gx = WRAP(X0 + r - 1);
            const unsigned gc = (unsigned)gx * NYg + (Y0 + cy);
            rS[r * CW + cy + 1] = rho[gc];
            uS[r * CW + cy + 1] = u[gc];
        } else if (c < NROWS * 64 + 2 * NROWS) {   // 36 edge cells
            const int e = c - NROWS * 64, r = e >> 1, side = e & 1;
            const int gx = WRAP(X0 + r - 1);
            const int gy = WRAP(side ? (Y0 + TW) : (Y0 - 1));
            const unsigned gc = (unsigned)gx * NYg + gy;
            rS[r * CW + (side ? 65 : 0)] = rho[gc];
            uS[r * CW + (side ? 65 : 0)] = u[gc];
            const float* fc = f + (size_t)gc * 9;
            const int base = r * RSTRIDE + (side ? EDGE_HI : EDGE_LO);
            #pragma unroll
            for (int q = 0; q < 9; q++) fs[base + q] = fc[q];
        }
    }
    __syncthreads();   // the ONLY barrier

    // ---- Phase 2: gather + collide + bounce-back + macro + store ----
    const int   EXq[9]  = {0, 1, 0, -1,  0, 1, -1, -1,  1};
    const int   EYq[9]  = {0, 0, 1,  0, -1, 1,  1, -1, -1};
    const float Wq[9]   = {4.0f/9.0f,
                           1.0f/9.0f, 1.0f/9.0f, 1.0f/9.0f, 1.0f/9.0f,
                           1.0f/36.0f, 1.0f/36.0f, 1.0f/36.0f, 1.0f/36.0f};
    const int   OPPq[9] = {0, 3, 4, 1, 2, 7, 8, 5, 6};
    const float INV_TAU = 1.0f / 0.6f;
    const float CREM    = 1.0f - INV_TAU;

    // fs y-offsets per EY class (edge slots via select)
    const int offY[3] = { (ly == 0)  ? EDGE_LO : (ly - 1) * 9,   // EY=+1
                          ly * 9,                                 // EY= 0
                          (ly == 63) ? EDGE_HI : (ly + 1) * 9 }; // EY=-1

    #pragma unroll
    for (int cp = 0; cp < 2; cp++) {
        const int lx = lx0 + 8 * cp;                 // 0..15
        const unsigned cell = (unsigned)(X0 + lx) * NYg + (Y0 + ly);
        const bool  sol = solid[cp];
        const float sgn = sol ? -1.0f : 1.0f;

        const int rowB[3]  = { lx * RSTRIDE, (lx + 1) * RSTRIDE, (lx + 2) * RSTRIDE };
        const int cRowB[3] = { lx * CW,      (lx + 1) * CW,      (lx + 2) * CW };
        const int fo_self  = (lx + 1) * RSTRIDE + ly * 9;
        const int co_self  = (lx + 1) * CW + (ly + 1);

        float fn[9];
        #pragma unroll
        for (int q = 0; q < 9; q++) {
            const int dx = EXq[q], dy = EYq[q];
            const int fo = sol ? (fo_self + OPPq[q])
                               : (rowB[1 - dx] + offY[1 - dy] + q);
            const int co = sol ? co_self
                               : (cRowB[1 - dx] + (ly + 1 - dy));
            const float  fv = fs[fo];
            const float  rr = rS[co];
            const float2 uv = uS[co];
            const float eu  = sgn * ((float)dx * uv.x + (float)dy * uv.y);
            const float usq = uv.x * uv.x + uv.y * uv.y;
            const float t   = 3.0f * rr * eu;
            const float feq = rr - 1.5f * rr * usq + t + 1.5f * t * eu;
            fn[q] = CREM * fv + (Wq[q] * INV_TAU) * feq;
        }

        float rn = 0.0f;
        #pragma unroll
        for (int q = 0; q < 9; q++) rn += fn[q];
        const float uxn = (fn[1] - fn[3]) + (fn[5] - fn[6]) + (fn[8] - fn[7]);
        const float uyn = (fn[2] - fn[4]) + (fn[5] + fn[6]) - (fn[7] + fn[8]);
        const float inv_rn = 1.0f / rn;

        // streaming stores: out never re-read, keep L2 for halo reuse
        float4* op = reinterpret_cast<float4*>(out + (size_t)cell * 12);
        __stcs(op + 0, make_float4(fn[0], fn[1], fn[2], fn[3]));
        __stcs(op + 1, make_float4(fn[4], fn[5], fn[6], fn[7]));
        __stcs(op + 2, make_float4(fn[8], rn, uxn * inv_rn, uyn * inv_rn));
    }
}

extern "C" void kernel_launch(void* const* d_in, const int* in_sizes, int n_in,
                              void* d_out, int out_size)
{
    const float*        f    = (const float*)d_in[0];
    const float*        rho  = (const float*)d_in[1];
    const float2*       u    = (const float2*)d_in[2];
    const unsigned int* mask = (const unsigned int*)d_in[3];
    float*              out  = (float*)d_out;

    cudaFuncSetAttribute(lbm_step_kernel,
                         cudaFuncAttributeMaxDynamicSharedMemorySize, SMEM_BYTES);

    dim3 block(512);
    dim3 grid(NYg / TW, NXg / TH);   // 32 x 128 = 4096 CTAs
    lbm_step_kernel<<<grid, block, SMEM_BYTES>>>(f, rho, u, mask, out);
}